// round 7
// baseline (speedup 1.0000x reference)
#include <cuda_runtime.h>
#include <cuda_bf16.h>
#include <math.h>
#include <stdint.h>

#define NMAX   50000
#define EMAX   800000
#define ETOT   (NMAX + EMAX)
#define HDIM   256
#define NEG_SLOPE 0.2f
#define EPS    1e-16f

// ---------------- scratch ----------------
__device__ float g_bufA[(size_t)NMAX * HDIM];
__device__ float g_bufB[(size_t)NMAX * HDIM];
__device__ float g_WT[768 * HDIM];
__device__ float g_asrc[NMAX];
__device__ float g_adst[NMAX];
__device__ float g_gate[NMAX];
__device__ int   g_counts[NMAX];
__device__ int   g_fill[NMAX];
__device__ int   g_rowptr[NMAX + 1];
__device__ int   g_csrc[ETOT];
__device__ float g_stats[2];
__device__ float g_partial[256 * 256];

// ---------------- helpers ----------------
__device__ __forceinline__ uint32_t s2u(const void* p) {
    uint32_t a;
    asm("{ .reg .u64 t; cvta.to.shared.u64 t, %1; cvt.u32.u64 %0, t; }" : "=r"(a) : "l"(p));
    return a;
}
__device__ __forceinline__ uint32_t b2u(__nv_bfloat16 a, __nv_bfloat16 b) {
    uint16_t ua = *(uint16_t*)&a, ub = *(uint16_t*)&b;
    return (uint32_t)ua | ((uint32_t)ub << 16);
}
__device__ __forceinline__ void cvt8(float4 v0, float4 v1, uint4& hi, uint4& lo) {
    float f[8] = {v0.x, v0.y, v0.z, v0.w, v1.x, v1.y, v1.z, v1.w};
    uint32_t h[4], l[4];
#pragma unroll
    for (int i = 0; i < 4; i++) {
        __nv_bfloat16 ha = __float2bfloat16_rn(f[2 * i]);
        __nv_bfloat16 hb = __float2bfloat16_rn(f[2 * i + 1]);
        float ra = f[2 * i] - __bfloat162float(ha);
        float rb = f[2 * i + 1] - __bfloat162float(hb);
        h[i] = b2u(ha, hb);
        l[i] = b2u(__float2bfloat16_rn(ra), __float2bfloat16_rn(rb));
    }
    hi = make_uint4(h[0], h[1], h[2], h[3]);
    lo = make_uint4(l[0], l[1], l[2], l[3]);
}
__device__ __forceinline__ void ldsm4(uint32_t& r0, uint32_t& r1, uint32_t& r2,
                                      uint32_t& r3, uint32_t addr) {
    asm volatile("ldmatrix.sync.aligned.m8n8.x4.shared.b16 {%0,%1,%2,%3}, [%4];"
                 : "=r"(r0), "=r"(r1), "=r"(r2), "=r"(r3) : "r"(addr));
}
#define MMA_BF16(c, a, b) \
    asm volatile("mma.sync.aligned.m16n8k16.row.col.f32.bf16.bf16.f32 " \
        "{%0,%1,%2,%3}, {%4,%5,%6,%7}, {%8,%9}, {%0,%1,%2,%3};" \
        : "+f"((c)[0]), "+f"((c)[1]), "+f"((c)[2]), "+f"((c)[3]) \
        : "r"((a)[0]), "r"((a)[1]), "r"((a)[2]), "r"((a)[3]), \
          "r"((b)[0]), "r"((b)[1]))

// ---------------- CSR build ----------------
__global__ void k_init_counts(int N) {
    int i = blockIdx.x * blockDim.x + threadIdx.x;
    if (i < N) { g_counts[i] = 1; g_fill[i] = 0; }
}
__global__ void k_hist(const int* __restrict__ ei, int E) {
    int e = blockIdx.x * blockDim.x + threadIdx.x;
    if (e < E) atomicAdd(&g_counts[ei[E + e]], 1);
}
__global__ void k_scan(int N) {
    __shared__ int ssum[1024];
    int t = threadIdx.x;
    int chunk = (N + 1023) / 1024;
    int start = t * chunk, end = min(start + chunk, N);
    int s = 0;
    for (int i = start; i < end; i++) s += g_counts[i];
    ssum[t] = s;
    __syncthreads();
    for (int off = 1; off < 1024; off <<= 1) {
        int v = ssum[t];
        int add = (t >= off) ? ssum[t - off] : 0;
        __syncthreads();
        ssum[t] = v + add;
        __syncthreads();
    }
    int run = (t == 0) ? 0 : ssum[t - 1];
    for (int i = start; i < end; i++) { g_rowptr[i] = run; run += g_counts[i]; }
    if (t == 1023) g_rowptr[N] = run;
}
__global__ void k_scatter(const int* __restrict__ ei, int N, int E) {
    int i = blockIdx.x * blockDim.x + threadIdx.x;
    if (i >= N + E) return;
    int s, d;
    if (i < N) { s = i; d = i; }
    else { s = ei[i - N]; d = ei[E + i - N]; }
    int pos = g_rowptr[d] + atomicAdd(&g_fill[d], 1);
    g_csrc[pos] = s;
}

// ---------------- weight transpose ----------------
__global__ void k_transpose(const float* __restrict__ W, float* __restrict__ WT,
                            int K, int N) {
    __shared__ float t[32][33];
    int bx = blockIdx.x * 32, by = blockIdx.y * 32;
    int tx = threadIdx.x, ty = threadIdx.y;
#pragma unroll
    for (int j = 0; j < 4; j++) {
        int k = by + ty + j * 8;
        if (k < K && bx + tx < N) t[ty + j * 8][tx] = W[(size_t)k * N + bx + tx];
    }
    __syncthreads();
#pragma unroll
    for (int j = 0; j < 4; j++) {
        int n = bx + ty + j * 8;
        int k = by + tx;
        if (n < N && k < K) WT[(size_t)n * K + k] = t[tx][ty + j * 8];
    }
}

// ---------------- 3xBF16 tensor-core GEMM, double-buffered ----------------
#define ROWB 80
#define OFF_AH 0
#define OFF_AL 10240
#define OFF_BH 20480
#define OFF_BL 30720
#define BUFSZ  40960
#define SMEM_GEMM (2 * BUFSZ)

extern __shared__ __align__(16) uint8_t smx[];

__global__ __launch_bounds__(256) void k_gemm_bf16(
        const float* __restrict__ A, const float* __restrict__ WT,
        float* __restrict__ C, int M, int K) {
    uint32_t sb = s2u(smx);
    int tid = threadIdx.x;
    int lane = tid & 31, wid = tid >> 5;
    int warp_m = wid >> 2, warp_n = wid & 3;
    int m0 = blockIdx.x * 128, n0 = blockIdx.y * 128;
    int rowsValid = M - m0;
    int nch = K >> 5;

    float c[4][4][4];
#pragma unroll
    for (int i = 0; i < 4; i++)
#pragma unroll
        for (int j = 0; j < 4; j++)
#pragma unroll
            for (int r = 0; r < 4; r++) c[i][j][r] = 0.f;

    int um = tid >> 2, ukq = tid & 3;            // unit i: row um or um+64
    // ldmatrix bases
    int r16 = lane & 15, cblk = lane >> 4;
    uint32_t aBase = (uint32_t)(warp_m * 64 + r16) * ROWB + cblk * 16;
    uint32_t bn = (lane & 7) + ((lane >> 4) << 3);
    uint32_t bkb = (lane >> 3) & 1;
    uint32_t bBase = (uint32_t)(warp_n * 32 + bn) * ROWB + bkb * 16;

    float4 ra0[2], ra1[2], rb0[2], rb1[2];

    // prologue: load chunk 0
#pragma unroll
    for (int i = 0; i < 2; i++) {
        int m = um + i * 64;
        if (m < rowsValid) {
            const float* p = A + (size_t)(m0 + m) * K + ukq * 8;
            ra0[i] = *(const float4*)p;
            ra1[i] = *(const float4*)(p + 4);
        } else {
            ra0[i] = make_float4(0.f, 0.f, 0.f, 0.f);
            ra1[i] = ra0[i];
        }
        const float* q = WT + (size_t)(n0 + m) * K + ukq * 8;
        rb0[i] = *(const float4*)q;
        rb1[i] = *(const float4*)(q + 4);
    }
    // store chunk 0 -> buf 0
#pragma unroll
    for (int i = 0; i < 2; i++) {
        int m = um + i * 64;
        uint4 hi, lo;
        cvt8(ra0[i], ra1[i], hi, lo);
        *(uint4*)(smx + OFF_AH + m * ROWB + ukq * 16) = hi;
        *(uint4*)(smx + OFF_AL + m * ROWB + ukq * 16) = lo;
        cvt8(rb0[i], rb1[i], hi, lo);
        *(uint4*)(smx + OFF_BH + m * ROWB + ukq * 16) = hi;
        *(uint4*)(smx + OFF_BL + m * ROWB + ukq * 16) = lo;
    }
    __syncthreads();

    for (int cch = 0; cch < nch; cch++) {
        uint32_t cur = (cch & 1) * BUFSZ;
        // prefetch next chunk into registers
        if (cch + 1 < nch) {
            int k0 = (cch + 1) * 32;
#pragma unroll
            for (int i = 0; i < 2; i++) {
                int m = um + i * 64;
                if (m < rowsValid) {
                    const float* p = A + (size_t)(m0 + m) * K + k0 + ukq * 8;
                    ra0[i] = *(const float4*)p;
                    ra1[i] = *(const float4*)(p + 4);
                } else {
                    ra0[i] = make_float4(0.f, 0.f, 0.f, 0.f);
                    ra1[i] = ra0[i];
                }
                const float* q = WT + (size_t)(n0 + m) * K + k0 + ukq * 8;
                rb0[i] = *(const float4*)q;
                rb1[i] = *(const float4*)(q + 4);
            }
        }
        // compute on current buffer
#pragma unroll
        for (int kt = 0; kt < 2; kt++) {
            uint32_t ah[4][4], al[4][4], bh[4][2], bl[4][2];
#pragma unroll
            for (int mi = 0; mi < 4; mi++) {
                uint32_t off = cur + aBase + (uint32_t)(mi * 16) * ROWB + kt * 32;
                ldsm4(ah[mi][0], ah[mi][1], ah[mi][2], ah[mi][3], sb + OFF_AH + off);
                ldsm4(al[mi][0], al[mi][1], al[mi][2], al[mi][3], sb + OFF_AL + off);
            }
#pragma unroll
            for (int np = 0; np < 2; np++) {
                uint32_t off = cur + bBase + (uint32_t)(np * 16) * ROWB + kt * 32;
                ldsm4(bh[np * 2][0], bh[np * 2][1], bh[np * 2 + 1][0], bh[np * 2 + 1][1],
                      sb + OFF_BH + off);
                ldsm4(bl[np * 2][0], bl[np * 2][1], bl[np * 2 + 1][0], bl[np * 2 + 1][1],
                      sb + OFF_BL + off);
            }
#pragma unroll
            for (int mi = 0; mi < 4; mi++)
#pragma unroll
                for (int ni = 0; ni < 4; ni++) {
                    MMA_BF16(c[mi][ni], ah[mi], bh[ni]);
                    MMA_BF16(c[mi][ni], ah[mi], bl[ni]);
                    MMA_BF16(c[mi][ni], al[mi], bh[ni]);
                }
        }
        // store next chunk to alternate buffer
        if (cch + 1 < nch) {
            uint32_t nxt = ((cch + 1) & 1) * BUFSZ;
#pragma unroll
            for (int i = 0; i < 2; i++) {
                int m = um + i * 64;
                uint4 hi, lo;
                cvt8(ra0[i], ra1[i], hi, lo);
                *(uint4*)(smx + nxt + OFF_AH + m * ROWB + ukq * 16) = hi;
                *(uint4*)(smx + nxt + OFF_AL + m * ROWB + ukq * 16) = lo;
                cvt8(rb0[i], rb1[i], hi, lo);
                *(uint4*)(smx + nxt + OFF_BH + m * ROWB + ukq * 16) = hi;
                *(uint4*)(smx + nxt + OFF_BL + m * ROWB + ukq * 16) = lo;
            }
        }
        __syncthreads();
    }

    // epilogue
    int g = lane >> 2, t4 = lane & 3;
#pragma unroll
    for (int mi = 0; mi < 4; mi++) {
#pragma unroll
        for (int ni = 0; ni < 4; ni++) {
            int m = m0 + warp_m * 64 + mi * 16 + g;
            int n = n0 + warp_n * 32 + ni * 8 + t4 * 2;
            if (m < M)
                *(float2*)(C + (size_t)m * HDIM + n) = make_float2(c[mi][ni][0], c[mi][ni][1]);
            if (m + 8 < M)
                *(float2*)(C + (size_t)(m + 8) * HDIM + n) = make_float2(c[mi][ni][2], c[mi][ni][3]);
        }
    }
}

// ---------------- per-node attention scalars ----------------
__global__ void k_attvec(const float* __restrict__ h, const float* __restrict__ vs,
                         const float* __restrict__ vd) {
    int n = blockIdx.x, t = threadIdx.x;
    __shared__ float r1[256], r2[256];
    float v = h[(size_t)n * HDIM + t];
    r1[t] = v * vs[t];
    r2[t] = v * vd[t];
    __syncthreads();
    for (int off = 128; off > 0; off >>= 1) {
        if (t < off) { r1[t] += r1[t + off]; r2[t] += r2[t + off]; }
        __syncthreads();
    }
    if (t == 0) { g_asrc[n] = r1[0]; g_adst[n] = r2[0]; }
}

// ---------------- edge softmax + aggregation (vectorized gather) ----------------
// 256 threads: 4 edge-slots x 64 col-groups (float4). Optional fused gate.
__global__ void k_agg(const float* __restrict__ hin, const float* __restrict__ bias,
                      float* __restrict__ hout, const float* __restrict__ gw,
                      const float* __restrict__ gb, int do_gate) {
    int n = blockIdx.x, t = threadIdx.x;
    int begin = g_rowptr[n], end = g_rowptr[n + 1];
    float ad = g_adst[n];
    __shared__ float sw[256];
    __shared__ int   ss[256];
    __shared__ float red[256];
    __shared__ float4 redv[192];

    // pass 1: segment max
    float m = -1e30f;
    for (int e = begin + t; e < end; e += 256) {
        float v = g_asrc[g_csrc[e]] + ad;
        v = v > 0.f ? v : NEG_SLOPE * v;
        m = fmaxf(m, v);
    }
    red[t] = m; __syncthreads();
    for (int off = 128; off > 0; off >>= 1) {
        if (t < off) red[t] = fmaxf(red[t], red[t + off]);
        __syncthreads();
    }
    m = red[0];

    // pass 2: weights + vectorized gather (4 edges in flight)
    int grp = t >> 6, col = t & 63;
    float4 acc = make_float4(0.f, 0.f, 0.f, 0.f);
    float lsum = 0.f;
    for (int cs = begin; cs < end; cs += 256) {
        int cnt = min(256, end - cs);
        __syncthreads();
        if (t < cnt) {
            int s = g_csrc[cs + t];
            float v = g_asrc[s] + ad;
            v = v > 0.f ? v : NEG_SLOPE * v;
            float w = expf(v - m);
            sw[t] = w; ss[t] = s; lsum += w;
        }
        __syncthreads();
        for (int j = grp; j < cnt; j += 4) {
            float w = sw[j];
            int s = ss[j];
            float4 v = *(const float4*)(hin + (size_t)s * HDIM + col * 4);
            acc.x += w * v.x; acc.y += w * v.y; acc.z += w * v.z; acc.w += w * v.w;
        }
    }
    __syncthreads();
    red[t] = lsum; __syncthreads();
    for (int off = 128; off > 0; off >>= 1) {
        if (t < off) red[t] += red[t + off];
        __syncthreads();
    }
    float S = red[0];
    __syncthreads();

    // cross-group reduce
    if (grp > 0) redv[(grp - 1) * 64 + col] = acc;
    __syncthreads();
    if (grp == 0) {
        float4 a1 = redv[col], a2 = redv[64 + col], a3 = redv[128 + col];
        acc.x += a1.x + a2.x + a3.x;
        acc.y += a1.y + a2.y + a3.y;
        acc.z += a1.z + a2.z + a3.z;
        acc.w += a1.w + a2.w + a3.w;
        float inv = 1.f / (S + EPS);
        float4 b4 = *(const float4*)(bias + col * 4);
        float4 o;
        o.x = fmaxf(acc.x * inv + b4.x, 0.f);
        o.y = fmaxf(acc.y * inv + b4.y, 0.f);
        o.z = fmaxf(acc.z * inv + b4.z, 0.f);
        o.w = fmaxf(acc.w * inv + b4.w, 0.f);
        *(float4*)(hout + (size_t)n * HDIM + col * 4) = o;
        if (do_gate) {
            float4 g4 = *(const float4*)(gw + col * 4);
            red[col] = o.x * g4.x + o.y * g4.y + o.z * g4.z + o.w * g4.w;
        }
    }
    if (do_gate) {
        __syncthreads();
        if (t < 32) {
            float v = red[t] + red[t + 32];
            for (int off = 16; off > 0; off >>= 1)
                v += __shfl_down_sync(0xffffffff, v, off);
            if (t == 0) g_gate[n] = v + gb[0];
        }
    }
}

// ---------------- global attention pooling ----------------
__global__ void k_softmax_stats(int N) {
    __shared__ float red[1024];
    int t = threadIdx.x;
    float m = -1e30f;
    for (int i = t; i < N; i += 1024) m = fmaxf(m, g_gate[i]);
    red[t] = m; __syncthreads();
    for (int off = 512; off > 0; off >>= 1) {
        if (t < off) red[t] = fmaxf(red[t], red[t + off]);
        __syncthreads();
    }
    m = red[0];
    __syncthreads();
    float s = 0.f;
    for (int i = t; i < N; i += 1024) s += expf(g_gate[i] - m);
    red[t] = s; __syncthreads();
    for (int off = 512; off > 0; off >>= 1) {
        if (t < off) red[t] += red[t + off];
        __syncthreads();
    }
    if (t == 0) { g_stats[0] = m; g_stats[1] = red[0]; }
}
__global__ void k_ga_partial(const float* __restrict__ h, int N) {
    int b = blockIdx.x, t = threadIdx.x;
    float m = g_stats[0], S = g_stats[1];
    float acc = 0.f;
    for (int n = b; n < N; n += 256)
        acc += (expf(g_gate[n] - m) / S) * h[(size_t)n * HDIM + t];
    g_partial[b * 256 + t] = acc;
}
__global__ void k_ga_final(float* __restrict__ out) {
    int t = threadIdx.x;
    float acc = 0.f;
    for (int b = 0; b < 256; b++) acc += g_partial[b * 256 + t];
    out[t] = acc;
}

// ---------------- launch ----------------
extern "C" void kernel_launch(void* const* d_in, const int* in_sizes, int n_in,
                              void* d_out, int out_size) {
    const float* x   = (const float*)d_in[0];
    const int*   ei  = (const int*)d_in[1];
    const float* W1  = (const float*)d_in[2];
    const float* b1  = (const float*)d_in[3];
    const float* as1 = (const float*)d_in[4];
    const float* ad1 = (const float*)d_in[5];
    const float* W2  = (const float*)d_in[6];
    const float* b2  = (const float*)d_in[7];
    const float* as2 = (const float*)d_in[8];
    const float* ad2 = (const float*)d_in[9];
    const float* gw  = (const float*)d_in[10];
    const float* gb  = (const float*)d_in[11];
    float*       out = (float*)d_out;

    const int D = 768;
    const int N = in_sizes[0] / D;
    const int E = in_sizes[1] / 2;

    float *bufA, *bufB, *wt;
    cudaGetSymbolAddress((void**)&bufA, g_bufA);
    cudaGetSymbolAddress((void**)&bufB, g_bufB);
    cudaGetSymbolAddress((void**)&wt,   g_WT);

    static int smemSet = 0;
    if (!smemSet) {
        cudaFuncSetAttribute(k_gemm_bf16, cudaFuncAttributeMaxDynamicSharedMemorySize,
                             SMEM_GEMM);
        smemSet = 1;
    }

    // CSR build
    k_init_counts<<<(N + 255) / 256, 256>>>(N);
    k_hist<<<(E + 255) / 256, 256>>>(ei, E);
    k_scan<<<1, 1024>>>(N);
    k_scatter<<<(N + E + 255) / 256, 256>>>(ei, N, E);

    dim3 gg((N + 127) / 128, 2);

    // layer 1
    k_transpose<<<dim3(HDIM / 32, D / 32), dim3(32, 8)>>>(W1, wt, D, HDIM);
    k_gemm_bf16<<<gg, 256, SMEM_GEMM>>>(x, wt, bufA, N, D);
    k_attvec<<<N, 256>>>(bufA, as1, ad1);
    k_agg<<<N, 256>>>(bufA, b1, bufB, gw, gb, 0);

    // layer 2
    k_transpose<<<dim3(HDIM / 32, HDIM / 32), dim3(32, 8)>>>(W2, wt, HDIM, HDIM);
    k_gemm_bf16<<<gg, 256, SMEM_GEMM>>>(bufB, wt, bufA, N, HDIM);
    k_attvec<<<N, 256>>>(bufA, as2, ad2);
    k_agg<<<N, 256>>>(bufA, b2, bufB, gw, gb, 1);

    // global attention pooling
    k_softmax_stats<<<1, 1024>>>(N);
    k_ga_partial<<<256, 256>>>(bufB, N);
    k_ga_final<<<1, 256>>>(out);
}

// round 8
// speedup vs baseline: 1.0545x; 1.0545x over previous
#include <cuda_runtime.h>
#include <cuda_bf16.h>
#include <math.h>
#include <stdint.h>

#define NMAX   50000
#define EMAX   800000
#define ETOT   (NMAX + EMAX)
#define HDIM   256
#define DMAX   768
#define NEG_SLOPE 0.2f
#define EPS    1e-16f

// ---------------- scratch ----------------
__device__ float g_bufA[(size_t)NMAX * HDIM];
__device__ float g_bufB[(size_t)NMAX * HDIM];
__device__ __nv_bfloat16 g_xh[(size_t)NMAX * DMAX];
__device__ __nv_bfloat16 g_xl[(size_t)NMAX * DMAX];
__device__ __nv_bfloat16 g_hh[(size_t)NMAX * HDIM];
__device__ __nv_bfloat16 g_hl[(size_t)NMAX * HDIM];
__device__ __nv_bfloat16 g_wth[HDIM * DMAX];
__device__ __nv_bfloat16 g_wtl[HDIM * DMAX];
__device__ float g_asrc[NMAX];
__device__ float g_adst[NMAX];
__device__ float g_gate[NMAX];
__device__ int   g_counts[NMAX];
__device__ int   g_fill[NMAX];
__device__ int   g_rowptr[NMAX + 1];
__device__ int   g_csrc[ETOT];
__device__ float g_stats[2];
__device__ float g_partial[256 * 256];

// ---------------- helpers ----------------
__device__ __forceinline__ uint32_t s2u(const void* p) {
    uint32_t a;
    asm("{ .reg .u64 t; cvta.to.shared.u64 t, %1; cvt.u32.u64 %0, t; }" : "=r"(a) : "l"(p));
    return a;
}
__device__ __forceinline__ uint32_t b2u(__nv_bfloat16 a, __nv_bfloat16 b) {
    uint16_t ua = *(uint16_t*)&a, ub = *(uint16_t*)&b;
    return (uint32_t)ua | ((uint32_t)ub << 16);
}
__device__ __forceinline__ void ldsm4(uint32_t& r0, uint32_t& r1, uint32_t& r2,
                                      uint32_t& r3, uint32_t addr) {
    asm volatile("ldmatrix.sync.aligned.m8n8.x4.shared.b16 {%0,%1,%2,%3}, [%4];"
                 : "=r"(r0), "=r"(r1), "=r"(r2), "=r"(r3) : "r"(addr));
}
#define MMA_BF16(c, a, b) \
    asm volatile("mma.sync.aligned.m16n8k16.row.col.f32.bf16.bf16.f32 " \
        "{%0,%1,%2,%3}, {%4,%5,%6,%7}, {%8,%9}, {%0,%1,%2,%3};" \
        : "+f"((c)[0]), "+f"((c)[1]), "+f"((c)[2]), "+f"((c)[3]) \
        : "r"((a)[0]), "r"((a)[1]), "r"((a)[2]), "r"((a)[3]), \
          "r"((b)[0]), "r"((b)[1]))
#define CP16(dst, src, sz) \
    asm volatile("cp.async.cg.shared.global [%0], [%1], 16, %2;" \
                 :: "r"(dst), "l"(src), "r"(sz) : "memory")
#define CP_COMMIT() asm volatile("cp.async.commit_group;" ::: "memory")
#define CP_WAIT1()  asm volatile("cp.async.wait_group 1;" ::: "memory")
#define CP_WAIT0()  asm volatile("cp.async.wait_group 0;" ::: "memory")

// ---------------- fp32 -> bf16 hi/lo split (planar) ----------------
__global__ void k_split(const float* __restrict__ in, __nv_bfloat16* __restrict__ hi,
                        __nv_bfloat16* __restrict__ lo, int total4) {
    int i = blockIdx.x * blockDim.x + threadIdx.x;
    if (i >= total4) return;
    float4 v = ((const float4*)in)[i];
    float f[4] = {v.x, v.y, v.z, v.w};
    __nv_bfloat16 h[4], l[4];
#pragma unroll
    for (int j = 0; j < 4; j++) {
        h[j] = __float2bfloat16_rn(f[j]);
        l[j] = __float2bfloat16_rn(f[j] - __bfloat162float(h[j]));
    }
    ((uint2*)hi)[i] = make_uint2(b2u(h[0], h[1]), b2u(h[2], h[3]));
    ((uint2*)lo)[i] = make_uint2(b2u(l[0], l[1]), b2u(l[2], l[3]));
}

// ---------------- CSR build ----------------
__global__ void k_init_counts(int N) {
    int i = blockIdx.x * blockDim.x + threadIdx.x;
    if (i < N) { g_counts[i] = 1; g_fill[i] = 0; }
}
__global__ void k_hist(const int* __restrict__ ei, int E) {
    int e = blockIdx.x * blockDim.x + threadIdx.x;
    if (e < E) atomicAdd(&g_counts[ei[E + e]], 1);
}
__global__ void k_scan(int N) {
    __shared__ int ssum[1024];
    int t = threadIdx.x;
    int chunk = (N + 1023) / 1024;
    int start = t * chunk, end = min(start + chunk, N);
    int s = 0;
    for (int i = start; i < end; i++) s += g_counts[i];
    ssum[t] = s;
    __syncthreads();
    for (int off = 1; off < 1024; off <<= 1) {
        int v = ssum[t];
        int add = (t >= off) ? ssum[t - off] : 0;
        __syncthreads();
        ssum[t] = v + add;
        __syncthreads();
    }
    int run = (t == 0) ? 0 : ssum[t - 1];
    for (int i = start; i < end; i++) { g_rowptr[i] = run; run += g_counts[i]; }
    if (t == 1023) g_rowptr[N] = run;
}
__global__ void k_scatter(const int* __restrict__ ei, int N, int E) {
    int i = blockIdx.x * blockDim.x + threadIdx.x;
    if (i >= N + E) return;
    int s, d;
    if (i < N) { s = i; d = i; }
    else { s = ei[i - N]; d = ei[E + i - N]; }
    int pos = g_rowptr[d] + atomicAdd(&g_fill[d], 1);
    g_csrc[pos] = s;
}

// ---------------- weight transpose + split: WT*[n][k] = split(W[k][n]) ----------------
__global__ void k_transpose_split(const float* __restrict__ W,
                                  __nv_bfloat16* __restrict__ WTh,
                                  __nv_bfloat16* __restrict__ WTl, int K, int N) {
    __shared__ float t[32][33];
    int bx = blockIdx.x * 32, by = blockIdx.y * 32;
    int tx = threadIdx.x, ty = threadIdx.y;
#pragma unroll
    for (int j = 0; j < 4; j++) {
        int k = by + ty + j * 8;
        if (k < K && bx + tx < N) t[ty + j * 8][tx] = W[(size_t)k * N + bx + tx];
    }
    __syncthreads();
#pragma unroll
    for (int j = 0; j < 4; j++) {
        int n = bx + ty + j * 8;
        int k = by + tx;
        if (n < N && k < K) {
            float v = t[tx][ty + j * 8];
            __nv_bfloat16 h = __float2bfloat16_rn(v);
            WTh[(size_t)n * K + k] = h;
            WTl[(size_t)n * K + k] = __float2bfloat16_rn(v - __bfloat162float(h));
        }
    }
}

// ---------------- 3xBF16 tensor-core GEMM, cp.async 2-stage pipeline ----------------
// C[M][256] = A[M][K] @ B^T.  A,B pre-split bf16 hi/lo.  Block 128x128, BK=32.
#define ROWB 80
#define OFF_AH 0
#define OFF_AL 10240
#define OFF_BH 20480
#define OFF_BL 30720
#define BUFSZ  40960
#define SMEM_GEMM (2 * BUFSZ)

extern __shared__ __align__(16) uint8_t smx[];

__global__ __launch_bounds__(256) void k_gemm_bf16(
        const __nv_bfloat16* __restrict__ Ah, const __nv_bfloat16* __restrict__ Al,
        const __nv_bfloat16* __restrict__ Bh, const __nv_bfloat16* __restrict__ Bl,
        float* __restrict__ C, int M, int K) {
    uint32_t sb = s2u(smx);
    int tid = threadIdx.x;
    int lane = tid & 31, wid = tid >> 5;
    int warp_m = wid >> 2, warp_n = wid & 3;
    int m0 = blockIdx.x * 128, n0 = blockIdx.y * 128;
    int rowsValid = M - m0;
    int nch = K >> 5;

    float c[4][4][4];
#pragma unroll
    for (int i = 0; i < 4; i++)
#pragma unroll
        for (int j = 0; j < 4; j++)
#pragma unroll
            for (int r = 0; r < 4; r++) c[i][j][r] = 0.f;

    // staging units: 512 x 16B per array; 256 threads x 2
    int um0 = tid >> 2, ukb = tid & 3;   // unit0: row um0, 16B-block ukb; unit1: row um0+64
    // ldmatrix bases
    int r16 = lane & 15, cblk = lane >> 4;
    uint32_t aBase = (uint32_t)(warp_m * 64 + r16) * ROWB + cblk * 16;
    uint32_t bn = (lane & 7) + ((lane >> 4) << 3);
    uint32_t bkb = (lane >> 3) & 1;
    uint32_t bBase = (uint32_t)(warp_n * 32 + bn) * ROWB + bkb * 16;

    // stage chunk cch into buffer at bufbase
    auto stage = [&](int cch, uint32_t bufbase) {
#pragma unroll
        for (int i = 0; i < 2; i++) {
            int m = um0 + i * 64;
            uint32_t doff = bufbase + m * ROWB + ukb * 16;
            uint32_t szA = (m < rowsValid) ? 16u : 0u;
            const __nv_bfloat16* pA = Ah + (size_t)(m0 + m) * K + cch * 32 + ukb * 8;
            const __nv_bfloat16* pAl = Al + (size_t)(m0 + m) * K + cch * 32 + ukb * 8;
            CP16(sb + OFF_AH + doff, pA, szA);
            CP16(sb + OFF_AL + doff, pAl, szA);
            const __nv_bfloat16* pB = Bh + (size_t)(n0 + m) * K + cch * 32 + ukb * 8;
            const __nv_bfloat16* pBl = Bl + (size_t)(n0 + m) * K + cch * 32 + ukb * 8;
            CP16(sb + OFF_BH + doff, pB, 16u);
            CP16(sb + OFF_BL + doff, pBl, 16u);
        }
    };

    stage(0, 0);
    CP_COMMIT();

    for (int cch = 0; cch < nch; cch++) {
        uint32_t cur = (uint32_t)(cch & 1) * BUFSZ;
        if (cch + 1 < nch) {
            stage(cch + 1, (uint32_t)((cch + 1) & 1) * BUFSZ);
            CP_COMMIT();
            CP_WAIT1();
        } else {
            CP_WAIT0();
        }
        __syncthreads();

#pragma unroll
        for (int kt = 0; kt < 2; kt++) {
            uint32_t ah[4][4], al[4][4], bh[4][2], bl[4][2];
#pragma unroll
            for (int mi = 0; mi < 4; mi++) {
                uint32_t off = cur + aBase + (uint32_t)(mi * 16) * ROWB + kt * 32;
                ldsm4(ah[mi][0], ah[mi][1], ah[mi][2], ah[mi][3], sb + OFF_AH + off);
                ldsm4(al[mi][0], al[mi][1], al[mi][2], al[mi][3], sb + OFF_AL + off);
            }
#pragma unroll
            for (int np = 0; np < 2; np++) {
                uint32_t off = cur + bBase + (uint32_t)(np * 16) * ROWB + kt * 32;
                ldsm4(bh[np * 2][0], bh[np * 2][1], bh[np * 2 + 1][0], bh[np * 2 + 1][1],
                      sb + OFF_BH + off);
                ldsm4(bl[np * 2][0], bl[np * 2][1], bl[np * 2 + 1][0], bl[np * 2 + 1][1],
                      sb + OFF_BL + off);
            }
#pragma unroll
            for (int mi = 0; mi < 4; mi++)
#pragma unroll
                for (int ni = 0; ni < 4; ni++) {
                    MMA_BF16(c[mi][ni], ah[mi], bh[ni]);
                    MMA_BF16(c[mi][ni], ah[mi], bl[ni]);
                    MMA_BF16(c[mi][ni], al[mi], bh[ni]);
                }
        }
        __syncthreads();
    }

    // epilogue
    int g = lane >> 2, t4 = lane & 3;
#pragma unroll
    for (int mi = 0; mi < 4; mi++) {
#pragma unroll
        for (int ni = 0; ni < 4; ni++) {
            int m = m0 + warp_m * 64 + mi * 16 + g;
            int n = n0 + warp_n * 32 + ni * 8 + t4 * 2;
            if (m < M)
                *(float2*)(C + (size_t)m * HDIM + n) = make_float2(c[mi][ni][0], c[mi][ni][1]);
            if (m + 8 < M)
                *(float2*)(C + (size_t)(m + 8) * HDIM + n) = make_float2(c[mi][ni][2], c[mi][ni][3]);
        }
    }
}

// ---------------- per-node attention scalars ----------------
__global__ void k_attvec(const float* __restrict__ h, const float* __restrict__ vs,
                         const float* __restrict__ vd) {
    int n = blockIdx.x, t = threadIdx.x;
    __shared__ float r1[256], r2[256];
    float v = h[(size_t)n * HDIM + t];
    r1[t] = v * vs[t];
    r2[t] = v * vd[t];
    __syncthreads();
    for (int off = 128; off > 0; off >>= 1) {
        if (t < off) { r1[t] += r1[t + off]; r2[t] += r2[t + off]; }
        __syncthreads();
    }
    if (t == 0) { g_asrc[n] = r1[0]; g_adst[n] = r2[0]; }
}

// ---------------- edge softmax + aggregation (R6 scalar version + split out) ----------------
__global__ void k_agg(const float* __restrict__ hin, const float* __restrict__ bias,
                      float* __restrict__ hout, __nv_bfloat16* __restrict__ oh,
                      __nv_bfloat16* __restrict__ ol, int do_split) {
    int n = blockIdx.x, t = threadIdx.x;
    int begin = g_rowptr[n], end = g_rowptr[n + 1];
    float ad = g_adst[n];
    __shared__ float sw[256];
    __shared__ int   ss[256];
    __shared__ float red[256];

    float m = -1e30f;
    for (int e = begin + t; e < end; e += 256) {
        float v = g_asrc[g_csrc[e]] + ad;
        v = v > 0.f ? v : NEG_SLOPE * v;
        m = fmaxf(m, v);
    }
    red[t] = m; __syncthreads();
    for (int off = 128; off > 0; off >>= 1) {
        if (t < off) red[t] = fmaxf(red[t], red[t + off]);
        __syncthreads();
    }
    m = red[0];
    __syncthreads();

    float acc = 0.f, lsum = 0.f;
    for (int cs = begin; cs < end; cs += 256) {
        int cnt = min(256, end - cs);
        if (t < cnt) {
            int s = g_csrc[cs + t];
            float v = g_asrc[s] + ad;
            v = v > 0.f ? v : NEG_SLOPE * v;
            float w = expf(v - m);
            sw[t] = w; ss[t] = s; lsum += w;
        }
        __syncthreads();
        for (int j = 0; j < cnt; j++)
            acc += sw[j] * hin[(size_t)ss[j] * HDIM + t];
        __syncthreads();
    }
    red[t] = lsum; __syncthreads();
    for (int off = 128; off > 0; off >>= 1) {
        if (t < off) red[t] += red[t + off];
        __syncthreads();
    }
    float S = red[0];
    float o = fmaxf(acc / (S + EPS) + bias[t], 0.f);
    hout[(size_t)n * HDIM + t] = o;
    if (do_split) {
        __nv_bfloat16 h = __float2bfloat16_rn(o);
        oh[(size_t)n * HDIM + t] = h;
        ol[(size_t)n * HDIM + t] = __float2bfloat16_rn(o - __bfloat162float(h));
    }
}

// ---------------- global attention ----------------
__global__ void k_gate(const float* __restrict__ h, const float* __restrict__ gw,
                       const float* __restrict__ gb) {
    int n = blockIdx.x, t = threadIdx.x;
    __shared__ float r[256];
    r[t] = h[(size_t)n * HDIM + t] * gw[t];
    __syncthreads();
    for (int off = 128; off > 0; off >>= 1) {
        if (t < off) r[t] += r[t + off];
        __syncthreads();
    }
    if (t == 0) g_gate[n] = r[0] + gb[0];
}
__global__ void k_softmax_stats(int N) {
    __shared__ float red[1024];
    int t = threadIdx.x;
    float m = -1e30f;
    for (int i = t; i < N; i += 1024) m = fmaxf(m, g_gate[i]);
    red[t] = m; __syncthreads();
    for (int off = 512; off > 0; off >>= 1) {
        if (t < off) red[t] = fmaxf(red[t], red[t + off]);
        __syncthreads();
    }
    m = red[0];
    __syncthreads();
    float s = 0.f;
    for (int i = t; i < N; i += 1024) s += expf(g_gate[i] - m);
    red[t] = s; __syncthreads();
    for (int off = 512; off > 0; off >>= 1) {
        if (t < off) red[t] += red[t + off];
        __syncthreads();
    }
    if (t == 0) { g_stats[0] = m; g_stats[1] = red[0]; }
}
__global__ void k_ga_partial(const float* __restrict__ h, int N) {
    int b = blockIdx.x, t = threadIdx.x;
    float m = g_stats[0], S = g_stats[1];
    float acc = 0.f;
    for (int n = b; n < N; n += 256)
        acc += (expf(g_gate[n] - m) / S) * h[(size_t)n * HDIM + t];
    g_partial[b * 256 + t] = acc;
}
__global__ void k_ga_final(float* __restrict__ out) {
    int t = threadIdx.x;
    float acc = 0.f;
    for (int b = 0; b < 256; b++) acc += g_partial[b * 256 + t];
    out[t] = acc;
}

// ---------------- launch ----------------
extern "C" void kernel_launch(void* const* d_in, const int* in_sizes, int n_in,
                              void* d_out, int out_size) {
    const float* x   = (const float*)d_in[0];
    const int*   ei  = (const int*)d_in[1];
    const float* W1  = (const float*)d_in[2];
    const float* b1  = (const float*)d_in[3];
    const float* as1 = (const float*)d_in[4];
    const float* ad1 = (const float*)d_in[5];
    const float* W2  = (const float*)d_in[6];
    const float* b2  = (const float*)d_in[7];
    const float* as2 = (const float*)d_in[8];
    const float* ad2 = (const float*)d_in[9];
    const float* gw  = (const float*)d_in[10];
    const float* gb  = (const float*)d_in[11];
    float*       out = (float*)d_out;

    const int D = 768;
    const int N = in_sizes[0] / D;
    const int E = in_sizes[1] / 2;

    float *bufA, *bufB;
    __nv_bfloat16 *xh, *xl, *hh, *hl, *wth, *wtl;
    cudaGetSymbolAddress((void**)&bufA, g_bufA);
    cudaGetSymbolAddress((void**)&bufB, g_bufB);
    cudaGetSymbolAddress((void**)&xh, g_xh);
    cudaGetSymbolAddress((void**)&xl, g_xl);
    cudaGetSymbolAddress((void**)&hh, g_hh);
    cudaGetSymbolAddress((void**)&hl, g_hl);
    cudaGetSymbolAddress((void**)&wth, g_wth);
    cudaGetSymbolAddress((void**)&wtl, g_wtl);

    cudaFuncSetAttribute(k_gemm_bf16, cudaFuncAttributeMaxDynamicSharedMemorySize,
                         SMEM_GEMM);

    // input split + CSR build
    int total4 = N * D / 4;
    k_split<<<(total4 + 255) / 256, 256>>>(x, xh, xl, total4);
    k_init_counts<<<(N + 255) / 256, 256>>>(N);
    k_hist<<<(E + 255) / 256, 256>>>(ei, E);
    k_scan<<<1, 1024>>>(N);
    k_scatter<<<(N + E + 255) / 256, 256>>>(ei, N, E);

    dim3 gg((N + 127) / 128, 2);

    // layer 1
    k_transpose_split<<<dim3(HDIM / 32, D / 32), dim3(32, 8)>>>(W1, wth, wtl, D, HDIM);
    k_gemm_bf16<<<gg, 256, SMEM_GEMM>>>(xh, xl, wth, wtl, bufA, N, D);
    k_attvec<<<N, 256>>>(bufA, as1, ad1);
    k_agg<<<N, 256>>>(bufA, b1, bufB, hh, hl, 1);

    // layer 2
    k_transpose_split<<<dim3(HDIM / 32, HDIM / 32), dim3(32, 8)>>>(W2, wth, wtl, HDIM, HDIM);
    k_gemm_bf16<<<gg, 256, SMEM_GEMM>>>(hh, hl, wth, wtl, bufA, N, HDIM);
    k_attvec<<<N, 256>>>(bufA, as2, ad2);
    k_agg<<<N, 256>>>(bufA, b2, bufB, hh, hl, 0);

    // global attention
    k_gate<<<N, 256>>>(bufB, gw, gb);
    k_softmax_stats<<<1, 1024>>>(N);
    k_ga_partial<<<256, 256>>>(bufB, N);
    k_ga_final<<<1, 256>>>(out);
}

// round 9
// speedup vs baseline: 1.6429x; 1.5580x over previous
#include <cuda_runtime.h>
#include <cuda_bf16.h>
#include <math.h>
#include <stdint.h>

#define NMAX   50000
#define EMAX   800000
#define ETOT   (NMAX + EMAX)
#define HDIM   256
#define DMAX   768
#define NEG_SLOPE 0.2f
#define EPS    1e-16f

// ---------------- scratch ----------------
__device__ float g_bufA[(size_t)NMAX * HDIM];
__device__ float g_bufB[(size_t)NMAX * HDIM];
__device__ __nv_bfloat16 g_xh[(size_t)NMAX * DMAX];
__device__ __nv_bfloat16 g_xl[(size_t)NMAX * DMAX];
__device__ __nv_bfloat16 g_hh[(size_t)NMAX * HDIM];
__device__ __nv_bfloat16 g_hl[(size_t)NMAX * HDIM];
__device__ __nv_bfloat16 g_wth[HDIM * DMAX];
__device__ __nv_bfloat16 g_wtl[HDIM * DMAX];
__device__ float g_asrc[NMAX];
__device__ float g_adst[NMAX];
__device__ float g_gate[NMAX];
__device__ int   g_counts[NMAX];
__device__ int   g_fill[NMAX];
__device__ int   g_rowptr[NMAX + 1];
__device__ int   g_csrc[ETOT];
__device__ float g_stats[2];
__device__ float g_partial[256 * 256];

// ---------------- helpers ----------------
__device__ __forceinline__ uint32_t s2u(const void* p) {
    uint32_t a;
    asm("{ .reg .u64 t; cvta.to.shared.u64 t, %1; cvt.u32.u64 %0, t; }" : "=r"(a) : "l"(p));
    return a;
}
__device__ __forceinline__ uint32_t b2u(__nv_bfloat16 a, __nv_bfloat16 b) {
    uint16_t ua = *(uint16_t*)&a, ub = *(uint16_t*)&b;
    return (uint32_t)ua | ((uint32_t)ub << 16);
}
__device__ __forceinline__ void ldsm4(uint32_t& r0, uint32_t& r1, uint32_t& r2,
                                      uint32_t& r3, uint32_t addr) {
    asm volatile("ldmatrix.sync.aligned.m8n8.x4.shared.b16 {%0,%1,%2,%3}, [%4];"
                 : "=r"(r0), "=r"(r1), "=r"(r2), "=r"(r3) : "r"(addr));
}
#define MMA_BF16(c, a, b) \
    asm volatile("mma.sync.aligned.m16n8k16.row.col.f32.bf16.bf16.f32 " \
        "{%0,%1,%2,%3}, {%4,%5,%6,%7}, {%8,%9}, {%0,%1,%2,%3};" \
        : "+f"((c)[0]), "+f"((c)[1]), "+f"((c)[2]), "+f"((c)[3]) \
        : "r"((a)[0]), "r"((a)[1]), "r"((a)[2]), "r"((a)[3]), \
          "r"((b)[0]), "r"((b)[1]))
#define CP16(dst, src, sz) \
    asm volatile("cp.async.cg.shared.global [%0], [%1], 16, %2;" \
                 :: "r"(dst), "l"(src), "r"(sz) : "memory")
#define CP_COMMIT() asm volatile("cp.async.commit_group;" ::: "memory")
#define CP_WAIT1()  asm volatile("cp.async.wait_group 1;" ::: "memory")
#define CP_WAIT0()  asm volatile("cp.async.wait_group 0;" ::: "memory")

// ---------------- fp32 -> bf16 hi/lo split (planar) ----------------
__global__ void k_split(const float* __restrict__ in, __nv_bfloat16* __restrict__ hi,
                        __nv_bfloat16* __restrict__ lo, int total4) {
    int i = blockIdx.x * blockDim.x + threadIdx.x;
    if (i >= total4) return;
    float4 v = ((const float4*)in)[i];
    float f[4] = {v.x, v.y, v.z, v.w};
    __nv_bfloat16 h[4], l[4];
#pragma unroll
    for (int j = 0; j < 4; j++) {
        h[j] = __float2bfloat16_rn(f[j]);
        l[j] = __float2bfloat16_rn(f[j] - __bfloat162float(h[j]));
    }
    ((uint2*)hi)[i] = make_uint2(b2u(h[0], h[1]), b2u(h[2], h[3]));
    ((uint2*)lo)[i] = make_uint2(b2u(l[0], l[1]), b2u(l[2], l[3]));
}

// ---------------- CSR build ----------------
__global__ void k_init_counts(int N) {
    int i = blockIdx.x * blockDim.x + threadIdx.x;
    if (i < N) { g_counts[i] = 1; g_fill[i] = 0; }
}
__global__ void k_hist(const int* __restrict__ ei, int E) {
    int e = blockIdx.x * blockDim.x + threadIdx.x;
    if (e < E) atomicAdd(&g_counts[ei[E + e]], 1);
}
__global__ void k_scan(int N) {
    __shared__ int ssum[1024];
    int t = threadIdx.x;
    int chunk = (N + 1023) / 1024;
    int start = t * chunk, end = min(start + chunk, N);
    int s = 0;
#pragma unroll 8
    for (int i = start; i < end; i++) s += g_counts[i];
    ssum[t] = s;
    __syncthreads();
    for (int off = 1; off < 1024; off <<= 1) {
        int v = ssum[t];
        int add = (t >= off) ? ssum[t - off] : 0;
        __syncthreads();
        ssum[t] = v + add;
        __syncthreads();
    }
    int run = (t == 0) ? 0 : ssum[t - 1];
#pragma unroll 8
    for (int i = start; i < end; i++) { g_rowptr[i] = run; run += g_counts[i]; }
    if (t == 1023) g_rowptr[N] = run;
}
__global__ void k_scatter(const int* __restrict__ ei, int N, int E) {
    int i = blockIdx.x * blockDim.x + threadIdx.x;
    if (i >= N + E) return;
    int s, d;
    if (i < N) { s = i; d = i; }
    else { s = ei[i - N]; d = ei[E + i - N]; }
    int pos = g_rowptr[d] + atomicAdd(&g_fill[d], 1);
    g_csrc[pos] = s;
}

// ---------------- weight transpose + split ----------------
__global__ void k_transpose_split(const float* __restrict__ W,
                                  __nv_bfloat16* __restrict__ WTh,
                                  __nv_bfloat16* __restrict__ WTl, int K, int N) {
    __shared__ float t[32][33];
    int bx = blockIdx.x * 32, by = blockIdx.y * 32;
    int tx = threadIdx.x, ty = threadIdx.y;
#pragma unroll
    for (int j = 0; j < 4; j++) {
        int k = by + ty + j * 8;
        if (k < K && bx + tx < N) t[ty + j * 8][tx] = W[(size_t)k * N + bx + tx];
    }
    __syncthreads();
#pragma unroll
    for (int j = 0; j < 4; j++) {
        int n = bx + ty + j * 8;
        int k = by + tx;
        if (n < N && k < K) {
            float v = t[tx][ty + j * 8];
            __nv_bfloat16 h = __float2bfloat16_rn(v);
            WTh[(size_t)n * K + k] = h;
            WTl[(size_t)n * K + k] = __float2bfloat16_rn(v - __bfloat162float(h));
        }
    }
}

// ---------------- 3xBF16 tensor-core GEMM (unchanged from R8) ----------------
#define ROWB 80
#define OFF_AH 0
#define OFF_AL 10240
#define OFF_BH 20480
#define OFF_BL 30720
#define BUFSZ  40960
#define SMEM_GEMM (2 * BUFSZ)

extern __shared__ __align__(16) uint8_t smx[];

__global__ __launch_bounds__(256) void k_gemm_bf16(
        const __nv_bfloat16* __restrict__ Ah, const __nv_bfloat16* __restrict__ Al,
        const __nv_bfloat16* __restrict__ Bh, const __nv_bfloat16* __restrict__ Bl,
        float* __restrict__ C, int M, int K) {
    uint32_t sb = s2u(smx);
    int tid = threadIdx.x;
    int lane = tid & 31, wid = tid >> 5;
    int warp_m = wid >> 2, warp_n = wid & 3;
    int m0 = blockIdx.x * 128, n0 = blockIdx.y * 128;
    int rowsValid = M - m0;
    int nch = K >> 5;

    float c[4][4][4];
#pragma unroll
    for (int i = 0; i < 4; i++)
#pragma unroll
        for (int j = 0; j < 4; j++)
#pragma unroll
            for (int r = 0; r < 4; r++) c[i][j][r] = 0.f;

    int um0 = tid >> 2, ukb = tid & 3;
    int r16 = lane & 15, cblk = lane >> 4;
    uint32_t aBase = (uint32_t)(warp_m * 64 + r16) * ROWB + cblk * 16;
    uint32_t bn = (lane & 7) + ((lane >> 4) << 3);
    uint32_t bkb = (lane >> 3) & 1;
    uint32_t bBase = (uint32_t)(warp_n * 32 + bn) * ROWB + bkb * 16;

    auto stage = [&](int cch, uint32_t bufbase) {
#pragma unroll
        for (int i = 0; i < 2; i++) {
            int m = um0 + i * 64;
            uint32_t doff = bufbase + m * ROWB + ukb * 16;
            uint32_t szA = (m < rowsValid) ? 16u : 0u;
            const __nv_bfloat16* pA = Ah + (size_t)(m0 + m) * K + cch * 32 + ukb * 8;
            const __nv_bfloat16* pAl = Al + (size_t)(m0 + m) * K + cch * 32 + ukb * 8;
            CP16(sb + OFF_AH + doff, pA, szA);
            CP16(sb + OFF_AL + doff, pAl, szA);
            const __nv_bfloat16* pB = Bh + (size_t)(n0 + m) * K + cch * 32 + ukb * 8;
            const __nv_bfloat16* pBl = Bl + (size_t)(n0 + m) * K + cch * 32 + ukb * 8;
            CP16(sb + OFF_BH + doff, pB, 16u);
            CP16(sb + OFF_BL + doff, pBl, 16u);
        }
    };

    stage(0, 0);
    CP_COMMIT();

    for (int cch = 0; cch < nch; cch++) {
        uint32_t cur = (uint32_t)(cch & 1) * BUFSZ;
        if (cch + 1 < nch) {
            stage(cch + 1, (uint32_t)((cch + 1) & 1) * BUFSZ);
            CP_COMMIT();
            CP_WAIT1();
        } else {
            CP_WAIT0();
        }
        __syncthreads();

#pragma unroll
        for (int kt = 0; kt < 2; kt++) {
            uint32_t ah[4][4], al[4][4], bh[4][2], bl[4][2];
#pragma unroll
            for (int mi = 0; mi < 4; mi++) {
                uint32_t off = cur + aBase + (uint32_t)(mi * 16) * ROWB + kt * 32;
                ldsm4(ah[mi][0], ah[mi][1], ah[mi][2], ah[mi][3], sb + OFF_AH + off);
                ldsm4(al[mi][0], al[mi][1], al[mi][2], al[mi][3], sb + OFF_AL + off);
            }
#pragma unroll
            for (int np = 0; np < 2; np++) {
                uint32_t off = cur + bBase + (uint32_t)(np * 16) * ROWB + kt * 32;
                ldsm4(bh[np * 2][0], bh[np * 2][1], bh[np * 2 + 1][0], bh[np * 2 + 1][1],
                      sb + OFF_BH + off);
                ldsm4(bl[np * 2][0], bl[np * 2][1], bl[np * 2 + 1][0], bl[np * 2 + 1][1],
                      sb + OFF_BL + off);
            }
#pragma unroll
            for (int mi = 0; mi < 4; mi++)
#pragma unroll
                for (int ni = 0; ni < 4; ni++) {
                    MMA_BF16(c[mi][ni], ah[mi], bh[ni]);
                    MMA_BF16(c[mi][ni], ah[mi], bl[ni]);
                    MMA_BF16(c[mi][ni], al[mi], bh[ni]);
                }
        }
        __syncthreads();
    }

    int g = lane >> 2, t4 = lane & 3;
#pragma unroll
    for (int mi = 0; mi < 4; mi++) {
#pragma unroll
        for (int ni = 0; ni < 4; ni++) {
            int m = m0 + warp_m * 64 + mi * 16 + g;
            int n = n0 + warp_n * 32 + ni * 8 + t4 * 2;
            if (m < M)
                *(float2*)(C + (size_t)m * HDIM + n) = make_float2(c[mi][ni][0], c[mi][ni][1]);
            if (m + 8 < M)
                *(float2*)(C + (size_t)(m + 8) * HDIM + n) = make_float2(c[mi][ni][2], c[mi][ni][3]);
        }
    }
}

// ---------------- warp-per-node attention scalars ----------------
__global__ __launch_bounds__(256) void k_attw(const float* __restrict__ h,
                                              const float* __restrict__ vs,
                                              const float* __restrict__ vd, int N) {
    int wid = threadIdx.x >> 5, lane = threadIdx.x & 31;
    int n = blockIdx.x * 8 + wid;
    if (n >= N) return;
    const float4* p = (const float4*)(h + (size_t)n * HDIM + lane * 8);
    float4 v0 = p[0], v1 = p[1];
    const float4* s = (const float4*)(vs + lane * 8);
    const float4* d = (const float4*)(vd + lane * 8);
    float4 s0 = s[0], s1 = s[1], d0 = d[0], d1 = d[1];
    float a_s = v0.x * s0.x + v0.y * s0.y + v0.z * s0.z + v0.w * s0.w
              + v1.x * s1.x + v1.y * s1.y + v1.z * s1.z + v1.w * s1.w;
    float a_d = v0.x * d0.x + v0.y * d0.y + v0.z * d0.z + v0.w * d0.w
              + v1.x * d1.x + v1.y * d1.y + v1.z * d1.z + v1.w * d1.w;
#pragma unroll
    for (int off = 16; off > 0; off >>= 1) {
        a_s += __shfl_xor_sync(0xffffffff, a_s, off);
        a_d += __shfl_xor_sync(0xffffffff, a_d, off);
    }
    if (lane == 0) { g_asrc[n] = a_s; g_adst[n] = a_d; }
}

// ---------------- warp-per-node edge softmax + aggregation ----------------
__global__ __launch_bounds__(256) void k_aggw(
        const float* __restrict__ hin, const float* __restrict__ bias,
        float* __restrict__ hout, __nv_bfloat16* __restrict__ oh,
        __nv_bfloat16* __restrict__ ol, const float* __restrict__ gw,
        const float* __restrict__ gb, int N, int do_split, int do_gate) {
    int wid = threadIdx.x >> 5, lane = threadIdx.x & 31;
    int n = blockIdx.x * 8 + wid;
    if (n >= N) return;
    int begin = g_rowptr[n], end = g_rowptr[n + 1];
    float ad = g_adst[n];

    // pass 1: segment max
    float m = -1e30f;
    for (int e = begin + lane; e < end; e += 32) {
        float v = g_asrc[g_csrc[e]] + ad;
        v = v > 0.f ? v : NEG_SLOPE * v;
        m = fmaxf(m, v);
    }
#pragma unroll
    for (int off = 16; off > 0; off >>= 1)
        m = fmaxf(m, __shfl_xor_sync(0xffffffff, m, off));

    // pass 2: batched weights + warp-wide gather (cols lane*8..lane*8+7)
    float4 acc0 = make_float4(0.f, 0.f, 0.f, 0.f);
    float4 acc1 = make_float4(0.f, 0.f, 0.f, 0.f);
    float lsum = 0.f;
    for (int eb = begin; eb < end; eb += 32) {
        int e = eb + lane;
        int cnt = min(32, end - eb);
        float w = 0.f;
        int sreg = 0;
        if (e < end) {
            sreg = g_csrc[e];
            float v = g_asrc[sreg] + ad;
            v = v > 0.f ? v : NEG_SLOPE * v;
            w = expf(v - m);
            lsum += w;
        }
        for (int j = 0; j < cnt; j++) {
            float wj = __shfl_sync(0xffffffff, w, j);
            int sj = __shfl_sync(0xffffffff, sreg, j);
            const float4* p = (const float4*)(hin + (size_t)sj * HDIM + lane * 8);
            float4 v0 = p[0], v1 = p[1];
            acc0.x += wj * v0.x; acc0.y += wj * v0.y;
            acc0.z += wj * v0.z; acc0.w += wj * v0.w;
            acc1.x += wj * v1.x; acc1.y += wj * v1.y;
            acc1.z += wj * v1.z; acc1.w += wj * v1.w;
        }
    }
#pragma unroll
    for (int off = 16; off > 0; off >>= 1)
        lsum += __shfl_xor_sync(0xffffffff, lsum, off);
    float inv = 1.f / (lsum + EPS);

    const float4* b4 = (const float4*)(bias + lane * 8);
    float4 bb0 = b4[0], bb1 = b4[1];
    float4 o0, o1;
    o0.x = fmaxf(acc0.x * inv + bb0.x, 0.f);
    o0.y = fmaxf(acc0.y * inv + bb0.y, 0.f);
    o0.z = fmaxf(acc0.z * inv + bb0.z, 0.f);
    o0.w = fmaxf(acc0.w * inv + bb0.w, 0.f);
    o1.x = fmaxf(acc1.x * inv + bb1.x, 0.f);
    o1.y = fmaxf(acc1.y * inv + bb1.y, 0.f);
    o1.z = fmaxf(acc1.z * inv + bb1.z, 0.f);
    o1.w = fmaxf(acc1.w * inv + bb1.w, 0.f);
    float4* po = (float4*)(hout + (size_t)n * HDIM + lane * 8);
    po[0] = o0; po[1] = o1;

    if (do_split) {
        float f[8] = {o0.x, o0.y, o0.z, o0.w, o1.x, o1.y, o1.z, o1.w};
        uint32_t hw[4], lw[4];
#pragma unroll
        for (int i = 0; i < 4; i++) {
            __nv_bfloat16 ha = __float2bfloat16_rn(f[2 * i]);
            __nv_bfloat16 hb = __float2bfloat16_rn(f[2 * i + 1]);
            hw[i] = b2u(ha, hb);
            lw[i] = b2u(__float2bfloat16_rn(f[2 * i] - __bfloat162float(ha)),
                        __float2bfloat16_rn(f[2 * i + 1] - __bfloat162float(hb)));
        }
        *(uint4*)(oh + (size_t)n * HDIM + lane * 8) = make_uint4(hw[0], hw[1], hw[2], hw[3]);
        *(uint4*)(ol + (size_t)n * HDIM + lane * 8) = make_uint4(lw[0], lw[1], lw[2], lw[3]);
    }
    if (do_gate) {
        const float4* g4 = (const float4*)(gw + lane * 8);
        float4 gg0 = g4[0], gg1 = g4[1];
        float gd = o0.x * gg0.x + o0.y * gg0.y + o0.z * gg0.z + o0.w * gg0.w
                 + o1.x * gg1.x + o1.y * gg1.y + o1.z * gg1.z + o1.w * gg1.w;
#pragma unroll
        for (int off = 16; off > 0; off >>= 1)
            gd += __shfl_xor_sync(0xffffffff, gd, off);
        if (lane == 0) g_gate[n] = gd + gb[0];
    }
}

// ---------------- global attention pooling ----------------
__global__ void k_softmax_stats(int N) {
    __shared__ float red[1024];
    int t = threadIdx.x;
    float m = -1e30f;
    for (int i = t; i < N; i += 1024) m = fmaxf(m, g_gate[i]);
    red[t] = m; __syncthreads();
    for (int off = 512; off > 0; off >>= 1) {
        if (t < off) red[t] = fmaxf(red[t], red[t + off]);
        __syncthreads();
    }
    m = red[0];
    __syncthreads();
    float s = 0.f;
    for (int i = t; i < N; i += 1024) s += expf(g_gate[i] - m);
    red[t] = s; __syncthreads();
    for (int off = 512; off > 0; off >>= 1) {
        if (t < off) red[t] += red[t + off];
        __syncthreads();
    }
    if (t == 0) { g_stats[0] = m; g_stats[1] = red[0]; }
}
__global__ void k_ga_partial(const float* __restrict__ h, int N) {
    int b = blockIdx.x, t = threadIdx.x;
    float m = g_stats[0], S = g_stats[1];
    float acc = 0.f;
    for (int n = b; n < N; n += 256)
        acc += (expf(g_gate[n] - m) / S) * h[(size_t)n * HDIM + t];
    g_partial[b * 256 + t] = acc;
}
__global__ void k_ga_final(float* __restrict__ out) {
    int t = threadIdx.x;
    float acc = 0.f;
    for (int b = 0; b < 256; b++) acc += g_partial[b * 256 + t];
    out[t] = acc;
}

// ---------------- launch ----------------
extern "C" void kernel_launch(void* const* d_in, const int* in_sizes, int n_in,
                              void* d_out, int out_size) {
    const float* x   = (const float*)d_in[0];
    const int*   ei  = (const int*)d_in[1];
    const float* W1  = (const float*)d_in[2];
    const float* b1  = (const float*)d_in[3];
    const float* as1 = (const float*)d_in[4];
    const float* ad1 = (const float*)d_in[5];
    const float* W2  = (const float*)d_in[6];
    const float* b2  = (const float*)d_in[7];
    const float* as2 = (const float*)d_in[8];
    const float* ad2 = (const float*)d_in[9];
    const float* gw  = (const float*)d_in[10];
    const float* gb  = (const float*)d_in[11];
    float*       out = (float*)d_out;

    const int D = 768;
    const int N = in_sizes[0] / D;
    const int E = in_sizes[1] / 2;

    float *bufA, *bufB;
    __nv_bfloat16 *xh, *xl, *hh, *hl, *wth, *wtl;
    cudaGetSymbolAddress((void**)&bufA, g_bufA);
    cudaGetSymbolAddress((void**)&bufB, g_bufB);
    cudaGetSymbolAddress((void**)&xh, g_xh);
    cudaGetSymbolAddress((void**)&xl, g_xl);
    cudaGetSymbolAddress((void**)&hh, g_hh);
    cudaGetSymbolAddress((void**)&hl, g_hl);
    cudaGetSymbolAddress((void**)&wth, g_wth);
    cudaGetSymbolAddress((void**)&wtl, g_wtl);

    cudaFuncSetAttribute(k_gemm_bf16, cudaFuncAttributeMaxDynamicSharedMemorySize,
                         SMEM_GEMM);

    // input split + CSR build
    int total4 = N * D / 4;
    k_split<<<(total4 + 255) / 256, 256>>>(x, xh, xl, total4);
    k_init_counts<<<(N + 255) / 256, 256>>>(N);
    k_hist<<<(E + 255) / 256, 256>>>(ei, E);
    k_scan<<<1, 1024>>>(N);
    k_scatter<<<(N + E + 255) / 256, 256>>>(ei, N, E);

    dim3 gg((N + 127) / 128, 2);
    int gw8 = (N + 7) / 8;

    // layer 1
    k_transpose_split<<<dim3(HDIM / 32, D / 32), dim3(32, 8)>>>(W1, wth, wtl, D, HDIM);
    k_gemm_bf16<<<gg, 256, SMEM_GEMM>>>(xh, xl, wth, wtl, bufA, N, D);
    k_attw<<<gw8, 256>>>(bufA, as1, ad1, N);
    k_aggw<<<gw8, 256>>>(bufA, b1, bufB, hh, hl, gw, gb, N, 1, 0);

    // layer 2
    k_transpose_split<<<dim3(HDIM / 32, HDIM / 32), dim3(32, 8)>>>(W2, wth, wtl, HDIM, HDIM);
    k_gemm_bf16<<<gg, 256, SMEM_GEMM>>>(hh, hl, wth, wtl, bufA, N, HDIM);
    k_attw<<<gw8, 256>>>(bufA, as2, ad2, N);
    k_aggw<<<gw8, 256>>>(bufA, b2, bufB, hh, hl, gw, gb, N, 0, 1);

    // global attention pooling
    k_softmax_stats<<<1, 1024>>>(N);
    k_ga_partial<<<256, 256>>>(bufB, N);
    k_ga_final<<<1, 256>>>(out);
}